// round 5
// baseline (speedup 1.0000x reference)
#include <cuda_runtime.h>
#include <math.h>
#include <stdint.h>

#define B_ 64
#define T_ 1024
#define H_ 256
#define M_ (B_*T_)   /* 65536 rows for the projection GEMMs */

// Scratch (device globals — no runtime allocation allowed)
__device__ float g_xp[B_*T_*H_];   // input-projection result for current layer
__device__ float g_h [B_*T_*H_];   // layer-0 hidden sequence

// ---------------------------------------------------------------------------
// packed f32x2 helpers (sm_100+): one instr = 2 fp32 FMAs
// ---------------------------------------------------------------------------
__device__ __forceinline__ unsigned long long ffma2(unsigned long long a,
                                                    unsigned long long b,
                                                    unsigned long long c) {
    unsigned long long d;
    asm("fma.rn.f32x2 %0, %1, %2, %3;" : "=l"(d) : "l"(a), "l"(b), "l"(c));
    return d;
}
__device__ __forceinline__ unsigned long long pack2(float lo, float hi) {
    unsigned long long r;
    asm("mov.b64 %0, {%1, %2};"
        : "=l"(r) : "r"(__float_as_uint(lo)), "r"(__float_as_uint(hi)));
    return r;
}
__device__ __forceinline__ float2 unpack2(unsigned long long v) {
    uint32_t lo, hi;
    asm("mov.b64 {%0, %1}, %2;" : "=r"(lo), "=r"(hi) : "l"(v));
    return make_float2(__uint_as_float(lo), __uint_as_float(hi));
}
__device__ __forceinline__ uint32_t smem_u32(const void* p) {
    return (uint32_t)__cvta_generic_to_shared(p);
}
// Fast accurate-enough tanh: ~1e-7 rel err, MUFU-based (no branches).
__device__ __forceinline__ float tanh_fast(float x) {
    float xc = fminf(fmaxf(x, -9.0f), 9.0f);     // tanh(9)=1-3e-8
    float e  = __expf(2.0f * xc);
    return __fdividef(e - 1.0f, e + 1.0f);
}

// ---------------------------------------------------------------------------
// Projection GEMM: out[M,256] = A[M,256] @ W[256,256]^T + bias
// (unchanged: ~214us each)
// ---------------------------------------------------------------------------
__global__ void __launch_bounds__(256, 2)
gemm_bias(const float* __restrict__ A, const float* __restrict__ W,
          const float* __restrict__ bias, float* __restrict__ out)
{
    __shared__ __align__(16) float As[16][128];
    __shared__ __align__(16) float Bs[16][64];

    const int tid = threadIdx.x;
    const int m0  = blockIdx.x * 128;
    const int n0  = blockIdx.y * 64;
    const int tx  = tid & 15;
    const int ty  = tid >> 4;
    const int lm  = tid >> 1;
    const int ak  = (tid & 1) * 8;
    const int ln  = tid & 63;
    const int bk  = (tid >> 6) * 4;

    unsigned long long acc[4][4];
#pragma unroll
    for (int p = 0; p < 4; p++)
#pragma unroll
        for (int n = 0; n < 4; n++) acc[p][n] = 0ull;

    const float* Arow = A + (size_t)(m0 + lm) * H_;
    const float* Wrow = W + (size_t)(n0 + ln) * H_;

    for (int k0 = 0; k0 < H_; k0 += 16) {
        float4 av0 = *(const float4*)(Arow + k0 + ak);
        float4 av1 = *(const float4*)(Arow + k0 + ak + 4);
        float4 bv0 = *(const float4*)(Wrow + k0 + bk);
        As[ak+0][lm] = av0.x; As[ak+1][lm] = av0.y;
        As[ak+2][lm] = av0.z; As[ak+3][lm] = av0.w;
        As[ak+4][lm] = av1.x; As[ak+5][lm] = av1.y;
        As[ak+6][lm] = av1.z; As[ak+7][lm] = av1.w;
        Bs[bk+0][ln] = bv0.x; Bs[bk+1][ln] = bv0.y;
        Bs[bk+2][ln] = bv0.z; Bs[bk+3][ln] = bv0.w;
        __syncthreads();
#pragma unroll
        for (int k = 0; k < 16; k++) {
            const ulonglong2* ap = (const ulonglong2*)&As[k][ty * 8];
            ulonglong2 q0 = ap[0];
            ulonglong2 q1 = ap[1];
            float4 bv = *(const float4*)&Bs[k][tx * 4];
            unsigned long long b0 = pack2(bv.x, bv.x);
            unsigned long long b1 = pack2(bv.y, bv.y);
            unsigned long long b2 = pack2(bv.z, bv.z);
            unsigned long long b3 = pack2(bv.w, bv.w);
            acc[0][0]=ffma2(q0.x,b0,acc[0][0]); acc[0][1]=ffma2(q0.x,b1,acc[0][1]);
            acc[0][2]=ffma2(q0.x,b2,acc[0][2]); acc[0][3]=ffma2(q0.x,b3,acc[0][3]);
            acc[1][0]=ffma2(q0.y,b0,acc[1][0]); acc[1][1]=ffma2(q0.y,b1,acc[1][1]);
            acc[1][2]=ffma2(q0.y,b2,acc[1][2]); acc[1][3]=ffma2(q0.y,b3,acc[1][3]);
            acc[2][0]=ffma2(q1.x,b0,acc[2][0]); acc[2][1]=ffma2(q1.x,b1,acc[2][1]);
            acc[2][2]=ffma2(q1.x,b2,acc[2][2]); acc[2][3]=ffma2(q1.x,b3,acc[2][3]);
            acc[3][0]=ffma2(q1.y,b0,acc[3][0]); acc[3][1]=ffma2(q1.y,b1,acc[3][1]);
            acc[3][2]=ffma2(q1.y,b2,acc[3][2]); acc[3][3]=ffma2(q1.y,b3,acc[3][3]);
        }
        __syncthreads();
    }

    float4 bb = *(const float4*)(bias + n0 + tx * 4);
#pragma unroll
    for (int p = 0; p < 4; p++) {
        float2 c0 = unpack2(acc[p][0]);
        float2 c1 = unpack2(acc[p][1]);
        float2 c2 = unpack2(acc[p][2]);
        float2 c3 = unpack2(acc[p][3]);
        float4 lo = make_float4(c0.x + bb.x, c1.x + bb.y, c2.x + bb.z, c3.x + bb.w);
        float4 hi = make_float4(c0.y + bb.x, c1.y + bb.y, c2.y + bb.z, c3.y + bb.w);
        size_t r = (size_t)(m0 + ty * 8 + 2 * p) * H_ + n0 + tx * 4;
        *(float4*)(out + r)      = lo;
        *(float4*)(out + r + H_) = hi;
    }
}

// ---------------------------------------------------------------------------
// Recurrent scan, round 3: mbarrier handshake with CORRECT ordering scopes.
//  Round-2 bug: remote arrive defaulted to release.CTA, which does not order
//  the preceding st.shared::cluster (a cluster-scope DSMEM write) against the
//  peer's acquire → stale h reads. Fix: release.cluster on the remote arrive.
//
//  - 2-CTA cluster per batch; each CTA: half of W_hh in registers.
//  - k-split by lane parity; 2-way reduce = shfl.xor(1); no __syncthreads.
//  - Double-buffered h in SMEM; per-buffer mbarrier, count 256 =
//    128 local arrivals (release.cta) + 128 remote arrivals (release.cluster).
//  - Consumer: try_wait.parity.acquire.cluster.
// ---------------------------------------------------------------------------
__device__ __forceinline__ void mbar_wait_cluster(uint32_t mbar, uint32_t parity) {
    asm volatile(
        "{\n\t"
        ".reg .pred P;\n"
        "WAIT_%=:\n\t"
        "mbarrier.try_wait.parity.acquire.cluster.shared::cta.b64 P, [%0], %1, 0x989680;\n\t"
        "@!P bra WAIT_%=;\n\t"
        "}"
        :: "r"(mbar), "r"(parity) : "memory");
}

__global__ void __launch_bounds__(256, 1) __cluster_dims__(2, 1, 1)
elman_scan(const float* __restrict__ xp, const float* __restrict__ Whh,
           float* __restrict__ ys)
{
    __shared__ __align__(16) float hs[2][2][136];   // [buf][khalf][128+8 pad]
    __shared__ __align__(8)  unsigned long long mbar[2];

    const int tid  = threadIdx.x;
    const int kpar = tid & 1;          // which k-half this thread reduces
    const int j    = tid >> 1;         // output index within CTA [0,128)
    const int rank = (int)(blockIdx.x & 1);
    const int batch= (int)(blockIdx.x >> 1);
    const int jg   = rank * 128 + j;   // global output index

    // Persistent weights: W_hh[jg][kpar*128 .. +127] as 64 packed f32x2
    unsigned long long w[64];
    {
        const ulonglong2* wv =
            (const ulonglong2*)(Whh + (size_t)jg * H_ + kpar * 128);
#pragma unroll
        for (int i = 0; i < 32; i++) {
            ulonglong2 v = wv[i];
            w[2*i] = v.x; w[2*i+1] = v.y;
        }
    }

    for (int i = tid; i < 2 * 2 * 136; i += 256) (&hs[0][0][0])[i] = 0.0f;
    const uint32_t mb0 = smem_u32(&mbar[0]);
    if (tid == 0) {
        asm volatile("mbarrier.init.shared.b64 [%0], 256;" :: "r"(mb0) : "memory");
        asm volatile("mbarrier.init.shared.b64 [%0], 256;" :: "r"(mb0 + 8) : "memory");
    }
    __syncthreads();
    // All inits/zeros visible cluster-wide before any remote traffic.
    asm volatile("barrier.cluster.arrive.aligned;" ::: "memory");
    asm volatile("barrier.cluster.wait.aligned;"   ::: "memory");

    // Peer addresses (same offsets in peer's SMEM window)
    const uint32_t hs0 = smem_u32(&hs[0][0][0]);
    uint32_t peer_hs, peer_mb;
    asm("mapa.shared::cluster.u32 %0, %1, %2;" : "=r"(peer_hs) : "r"(hs0), "r"(rank ^ 1));
    asm("mapa.shared::cluster.u32 %0, %1, %2;" : "=r"(peer_mb) : "r"(mb0), "r"(rank ^ 1));

    const float* xpb = xp + (size_t)batch * T_ * H_;
    float*       ysb = ys + (size_t)batch * T_ * H_;

    float x_cur = __ldg(xpb + jg);     // xp[t=0]
    float x_next = 0.0f;

    for (int t = 0; t < T_; t++) {
        if (t + 1 < T_)
            x_next = __ldg(xpb + (size_t)(t + 1) * H_ + jg);
        if (t)   // t=0 reads the zeroed buffer, no wait needed
            mbar_wait_cluster(mb0 + (uint32_t)(t & 1) * 8u,
                              (uint32_t)(((t - 1) >> 1) & 1));

        const ulonglong2* hv = (const ulonglong2*)&hs[t & 1][kpar][0];
        unsigned long long a0 = 0ull, a1 = 0ull, a2 = 0ull, a3 = 0ull;
#pragma unroll
        for (int i = 0; i < 16; i++) {
            ulonglong2 p = hv[2*i];
            ulonglong2 q = hv[2*i + 1];
            a0 = ffma2(w[4*i+0], p.x, a0);
            a1 = ffma2(w[4*i+1], p.y, a1);
            a2 = ffma2(w[4*i+2], q.x, a2);
            a3 = ffma2(w[4*i+3], q.y, a3);
        }
        float2 f0 = unpack2(a0), f1 = unpack2(a1);
        float2 f2 = unpack2(a2), f3 = unpack2(a3);
        float s = ((f0.x + f0.y) + (f1.x + f1.y)) +
                  ((f2.x + f2.y) + (f3.x + f3.y));
        float tot = s + __shfl_xor_sync(0xFFFFFFFFu, s, 1);
        float v = tanh_fast(tot + x_cur);

        if (kpar == 0) {
            ysb[(size_t)t * H_ + jg] = v;
            if (t + 1 < T_) {
                const int wb = (t + 1) & 1;
                hs[wb][rank][j] = v;                       // local half
                uint32_t off = (((uint32_t)wb * 2u + (uint32_t)rank) * 136u
                                + (uint32_t)j) * 4u;
                asm volatile("st.shared::cluster.f32 [%0], %1;"
                             :: "r"(peer_hs + off), "f"(v) : "memory");
                // local arrive: release.cta covers the own-half SMEM write
                asm volatile("mbarrier.arrive.release.cta.shared::cta.b64 _, [%0];"
                             :: "r"(mb0 + (uint32_t)wb * 8u) : "memory");
                // remote arrive: release.CLUSTER orders the DSMEM store above
                // against the peer's acquire-wait (this was the round-2 bug)
                asm volatile("mbarrier.arrive.release.cluster.shared::cluster.b64 _, [%0];"
                             :: "r"(peer_mb + (uint32_t)wb * 8u) : "memory");
            }
        }
        x_cur = x_next;
    }
    // Final iteration issues no remote traffic; every earlier remote op was
    // consumed by a completed acquire-wait, so plain exit is safe.
}

// ---------------------------------------------------------------------------
// Launch: gemm0 -> scan0 -> gemm1 -> scan1 (all on the capture stream)
// ---------------------------------------------------------------------------
extern "C" void kernel_launch(void* const* d_in, const int* in_sizes, int n_in,
                              void* d_out, int out_size)
{
    const float* x     = (const float*)d_in[0];
    const float* W_ih0 = (const float*)d_in[1];
    const float* b_ih0 = (const float*)d_in[2];
    const float* W_hh0 = (const float*)d_in[3];
    const float* W_ih1 = (const float*)d_in[4];
    const float* b_ih1 = (const float*)d_in[5];
    const float* W_hh1 = (const float*)d_in[6];
    float* out = (float*)d_out;

    float *xp, *h;
    cudaGetSymbolAddress((void**)&xp, g_xp);
    cudaGetSymbolAddress((void**)&h,  g_h);

    dim3 ggrid(M_ / 128, H_ / 64);   // (512, 4)

    gemm_bias<<<ggrid, 256>>>(x, W_ih0, b_ih0, xp);
    elman_scan<<<B_ * 2, 256>>>(xp, W_hh0, h);
    gemm_bias<<<ggrid, 256>>>(h, W_ih1, b_ih1, xp);
    elman_scan<<<B_ * 2, 256>>>(xp, W_hh1, out);
}

// round 6
// speedup vs baseline: 1.3171x; 1.3171x over previous
#include <cuda_runtime.h>
#include <math.h>
#include <stdint.h>

#define B_ 64
#define T_ 1024
#define H_ 256
#define M_ (B_*T_)   /* 65536 rows for the projection GEMMs */

// Scratch (device globals — no runtime allocation allowed)
__device__ float g_xp[B_*T_*H_];   // input-projection result for current layer
__device__ float g_h [B_*T_*H_];   // layer-0 hidden sequence

// ---------------------------------------------------------------------------
// packed f32x2 helpers (sm_100+): one instr = 2 fp32 FMAs
// ---------------------------------------------------------------------------
__device__ __forceinline__ unsigned long long ffma2(unsigned long long a,
                                                    unsigned long long b,
                                                    unsigned long long c) {
    unsigned long long d;
    asm("fma.rn.f32x2 %0, %1, %2, %3;" : "=l"(d) : "l"(a), "l"(b), "l"(c));
    return d;
}
__device__ __forceinline__ unsigned long long pack2(float lo, float hi) {
    unsigned long long r;
    asm("mov.b64 %0, {%1, %2};"
        : "=l"(r) : "r"(__float_as_uint(lo)), "r"(__float_as_uint(hi)));
    return r;
}
__device__ __forceinline__ float2 unpack2(unsigned long long v) {
    uint32_t lo, hi;
    asm("mov.b64 {%0, %1}, %2;" : "=r"(lo), "=r"(hi) : "l"(v));
    return make_float2(__uint_as_float(lo), __uint_as_float(hi));
}
__device__ __forceinline__ uint32_t smem_u32(const void* p) {
    return (uint32_t)__cvta_generic_to_shared(p);
}
// Fast accurate-enough tanh: ~1e-7 rel err, MUFU-based (no branches).
__device__ __forceinline__ float tanh_fast(float x) {
    float xc = fminf(fmaxf(x, -9.0f), 9.0f);     // tanh(9)=1-3e-8
    float e  = __expf(2.0f * xc);
    return __fdividef(e - 1.0f, e + 1.0f);
}

// ---------------------------------------------------------------------------
// Projection GEMM: out[M,256] = A[M,256] @ W[256,256]^T + bias
// (unchanged: ~214us each, ~40 TF/s — near fp32 SIMT ceiling)
// ---------------------------------------------------------------------------
__global__ void __launch_bounds__(256, 2)
gemm_bias(const float* __restrict__ A, const float* __restrict__ W,
          const float* __restrict__ bias, float* __restrict__ out)
{
    __shared__ __align__(16) float As[16][128];
    __shared__ __align__(16) float Bs[16][64];

    const int tid = threadIdx.x;
    const int m0  = blockIdx.x * 128;
    const int n0  = blockIdx.y * 64;
    const int tx  = tid & 15;
    const int ty  = tid >> 4;
    const int lm  = tid >> 1;
    const int ak  = (tid & 1) * 8;
    const int ln  = tid & 63;
    const int bk  = (tid >> 6) * 4;

    unsigned long long acc[4][4];
#pragma unroll
    for (int p = 0; p < 4; p++)
#pragma unroll
        for (int n = 0; n < 4; n++) acc[p][n] = 0ull;

    const float* Arow = A + (size_t)(m0 + lm) * H_;
    const float* Wrow = W + (size_t)(n0 + ln) * H_;

    for (int k0 = 0; k0 < H_; k0 += 16) {
        float4 av0 = *(const float4*)(Arow + k0 + ak);
        float4 av1 = *(const float4*)(Arow + k0 + ak + 4);
        float4 bv0 = *(const float4*)(Wrow + k0 + bk);
        As[ak+0][lm] = av0.x; As[ak+1][lm] = av0.y;
        As[ak+2][lm] = av0.z; As[ak+3][lm] = av0.w;
        As[ak+4][lm] = av1.x; As[ak+5][lm] = av1.y;
        As[ak+6][lm] = av1.z; As[ak+7][lm] = av1.w;
        Bs[bk+0][ln] = bv0.x; Bs[bk+1][ln] = bv0.y;
        Bs[bk+2][ln] = bv0.z; Bs[bk+3][ln] = bv0.w;
        __syncthreads();
#pragma unroll
        for (int k = 0; k < 16; k++) {
            const ulonglong2* ap = (const ulonglong2*)&As[k][ty * 8];
            ulonglong2 q0 = ap[0];
            ulonglong2 q1 = ap[1];
            float4 bv = *(const float4*)&Bs[k][tx * 4];
            unsigned long long b0 = pack2(bv.x, bv.x);
            unsigned long long b1 = pack2(bv.y, bv.y);
            unsigned long long b2 = pack2(bv.z, bv.z);
            unsigned long long b3 = pack2(bv.w, bv.w);
            acc[0][0]=ffma2(q0.x,b0,acc[0][0]); acc[0][1]=ffma2(q0.x,b1,acc[0][1]);
            acc[0][2]=ffma2(q0.x,b2,acc[0][2]); acc[0][3]=ffma2(q0.x,b3,acc[0][3]);
            acc[1][0]=ffma2(q0.y,b0,acc[1][0]); acc[1][1]=ffma2(q0.y,b1,acc[1][1]);
            acc[1][2]=ffma2(q0.y,b2,acc[1][2]); acc[1][3]=ffma2(q0.y,b3,acc[1][3]);
            acc[2][0]=ffma2(q1.x,b0,acc[2][0]); acc[2][1]=ffma2(q1.x,b1,acc[2][1]);
            acc[2][2]=ffma2(q1.x,b2,acc[2][2]); acc[2][3]=ffma2(q1.x,b3,acc[2][3]);
            acc[3][0]=ffma2(q1.y,b0,acc[3][0]); acc[3][1]=ffma2(q1.y,b1,acc[3][1]);
            acc[3][2]=ffma2(q1.y,b2,acc[3][2]); acc[3][3]=ffma2(q1.y,b3,acc[3][3]);
        }
        __syncthreads();
    }

    float4 bb = *(const float4*)(bias + n0 + tx * 4);
#pragma unroll
    for (int p = 0; p < 4; p++) {
        float2 c0 = unpack2(acc[p][0]);
        float2 c1 = unpack2(acc[p][1]);
        float2 c2 = unpack2(acc[p][2]);
        float2 c3 = unpack2(acc[p][3]);
        float4 lo = make_float4(c0.x + bb.x, c1.x + bb.y, c2.x + bb.z, c3.x + bb.w);
        float4 hi = make_float4(c0.y + bb.x, c1.y + bb.y, c2.y + bb.z, c3.y + bb.w);
        size_t r = (size_t)(m0 + ty * 8 + 2 * p) * H_ + n0 + tx * 4;
        *(float4*)(out + r)      = lo;
        *(float4*)(out + r + H_) = hi;
    }
}

// ---------------------------------------------------------------------------
// Recurrent scan, round 6: st.async + tx-counted mbarrier.
//  Round-5 lesson: cluster-scope acquire waits + 256 serialized arrivals per
//  phase cost ~2230 cyc/step. New handshake:
//   - Producers send their h value to the peer CTA with
//     st.async.shared::cluster.mbarrier::complete_tx::bytes (visibility is
//     carried by the mbarrier completion — no cluster-scope fence needed).
//   - Per buffer b, mbar[b]: 1 arrival (thread 0, arrive.expect_tx 512B)
//     + 512 tx bytes from the peer's 128 st.asyncs.
//   - Consumer: plain CTA-scope try_wait.parity (fast TRYWAIT path).
//   - Local half: plain STS, ordered by one bar.sync per step.
//  Hazards: buffer WAR protected by data dependence (st.async value derives
//  from reads of the recycled buffer); next-phase tx cannot precede this
//  phase's expect_tx (peer's next production is gated on a wait that needs
//  our expect-arrival); wait parity = ((t-1)>>1)&1.
// ---------------------------------------------------------------------------
__device__ __forceinline__ void mbar_wait_cta(uint32_t mbar, uint32_t parity) {
    asm volatile(
        "{\n\t"
        ".reg .pred P;\n"
        "WAIT_%=:\n\t"
        "mbarrier.try_wait.parity.shared::cta.b64 P, [%0], %1, 0x989680;\n\t"
        "@!P bra WAIT_%=;\n\t"
        "}"
        :: "r"(mbar), "r"(parity) : "memory");
}

__global__ void __launch_bounds__(256, 1) __cluster_dims__(2, 1, 1)
elman_scan(const float* __restrict__ xp, const float* __restrict__ Whh,
           float* __restrict__ ys)
{
    __shared__ __align__(16) float hs[2][2][136];   // [buf][khalf][128+8 pad]
    __shared__ __align__(8)  unsigned long long mbar[2];

    const int tid  = threadIdx.x;
    const int kpar = tid & 1;          // which k-half this thread reduces
    const int j    = tid >> 1;         // output index within CTA [0,128)
    const int rank = (int)(blockIdx.x & 1);
    const int batch= (int)(blockIdx.x >> 1);
    const int jg   = rank * 128 + j;   // global output index

    // Persistent weights: W_hh[jg][kpar*128 .. +127] as 64 packed f32x2
    unsigned long long w[64];
    {
        const ulonglong2* wv =
            (const ulonglong2*)(Whh + (size_t)jg * H_ + kpar * 128);
#pragma unroll
        for (int i = 0; i < 32; i++) {
            ulonglong2 v = wv[i];
            w[2*i] = v.x; w[2*i+1] = v.y;
        }
    }

    for (int i = tid; i < 2 * 2 * 136; i += 256) (&hs[0][0][0])[i] = 0.0f;
    const uint32_t mb0 = smem_u32(&mbar[0]);
    if (tid == 0) {
        asm volatile("mbarrier.init.shared.b64 [%0], 1;" :: "r"(mb0) : "memory");
        asm volatile("mbarrier.init.shared.b64 [%0], 1;" :: "r"(mb0 + 8) : "memory");
    }
    __syncthreads();
    // All inits/zeros visible cluster-wide before any remote traffic.
    asm volatile("barrier.cluster.arrive.aligned;" ::: "memory");
    asm volatile("barrier.cluster.wait.aligned;"   ::: "memory");

    // Peer addresses (same offsets in peer's SMEM window)
    const uint32_t hs0 = smem_u32(&hs[0][0][0]);
    uint32_t peer_hs, peer_mb;
    asm("mapa.shared::cluster.u32 %0, %1, %2;" : "=r"(peer_hs) : "r"(hs0), "r"(rank ^ 1));
    asm("mapa.shared::cluster.u32 %0, %1, %2;" : "=r"(peer_mb) : "r"(mb0), "r"(rank ^ 1));

    const float* xpb = xp + (size_t)batch * T_ * H_;
    float*       ysb = ys + (size_t)batch * T_ * H_;

    float x_cur = __ldg(xpb + jg);     // xp[t=0]
    float x_next = 0.0f;

    for (int t = 0; t < T_; t++) {
        if (t + 1 < T_)
            x_next = __ldg(xpb + (size_t)(t + 1) * H_ + jg);
        if (t)   // t=0 reads the zeroed buffer, no wait needed
            mbar_wait_cta(mb0 + (uint32_t)(t & 1) * 8u,
                          (uint32_t)(((t - 1) >> 1) & 1));
        // Open next phase: 1 arrival + expect 512 remote bytes. Legal here:
        // mbar[wb]'s previous phase completed at our wait in step t-1.
        if (tid == 0 && t + 1 < T_) {
            asm volatile("mbarrier.arrive.expect_tx.shared.b64 _, [%0], %1;"
                         :: "r"(mb0 + (uint32_t)(((t + 1) & 1)) * 8u),
                            "r"(512u) : "memory");
        }

        const ulonglong2* hv = (const ulonglong2*)&hs[t & 1][kpar][0];
        unsigned long long a0 = 0ull, a1 = 0ull, a2 = 0ull, a3 = 0ull;
#pragma unroll
        for (int i = 0; i < 16; i++) {
            ulonglong2 p = hv[2*i];
            ulonglong2 q = hv[2*i + 1];
            a0 = ffma2(w[4*i+0], p.x, a0);
            a1 = ffma2(w[4*i+1], p.y, a1);
            a2 = ffma2(w[4*i+2], q.x, a2);
            a3 = ffma2(w[4*i+3], q.y, a3);
        }
        float2 f0 = unpack2(a0), f1 = unpack2(a1);
        float2 f2 = unpack2(a2), f3 = unpack2(a3);
        float s = ((f0.x + f0.y) + (f1.x + f1.y)) +
                  ((f2.x + f2.y) + (f3.x + f3.y));
        float tot = s + __shfl_xor_sync(0xFFFFFFFFu, s, 1);
        float v = tanh_fast(tot + x_cur);

        if (kpar == 0 && t + 1 < T_) {
            const int wb = (t + 1) & 1;
            uint32_t off = (((uint32_t)wb * 2u + (uint32_t)rank) * 136u
                            + (uint32_t)j) * 4u;
            // Remote half: async store, tx-counted on the PEER's mbar[wb].
            asm volatile(
                "st.async.shared::cluster.mbarrier::complete_tx::bytes.b32 "
                "[%0], %1, [%2];"
                :: "r"(peer_hs + off), "r"(__float_as_uint(v)),
                   "r"(peer_mb + (uint32_t)wb * 8u) : "memory");
            hs[wb][rank][j] = v;                      // local half (plain STS)
        }
        if (kpar == 0)
            ysb[(size_t)t * H_ + jg] = v;
        __syncthreads();   // local-half visibility for step t+1 (drains STS)
        x_cur = x_next;
    }
}

// ---------------------------------------------------------------------------
// Launch: gemm0 -> scan0 -> gemm1 -> scan1 (all on the capture stream)
// ---------------------------------------------------------------------------
extern "C" void kernel_launch(void* const* d_in, const int* in_sizes, int n_in,
                              void* d_out, int out_size)
{
    const float* x     = (const float*)d_in[0];
    const float* W_ih0 = (const float*)d_in[1];
    const float* b_ih0 = (const float*)d_in[2];
    const float* W_hh0 = (const float*)d_in[3];
    const float* W_ih1 = (const float*)d_in[4];
    const float* b_ih1 = (const float*)d_in[5];
    const float* W_hh1 = (const float*)d_in[6];
    float* out = (float*)d_out;

    float *xp, *h;
    cudaGetSymbolAddress((void**)&xp, g_xp);
    cudaGetSymbolAddress((void**)&h,  g_h);

    dim3 ggrid(M_ / 128, H_ / 64);   // (512, 4)

    gemm_bias<<<ggrid, 256>>>(x, W_ih0, b_ih0, xp);
    elman_scan<<<B_ * 2, 256>>>(xp, W_hh0, h);
    gemm_bias<<<ggrid, 256>>>(h, W_ih1, b_ih1, xp);
    elman_scan<<<B_ * 2, 256>>>(xp, W_hh1, out);
}

// round 7
// speedup vs baseline: 1.3228x; 1.0043x over previous
#include <cuda_runtime.h>
#include <math.h>
#include <stdint.h>

#define B_ 64
#define T_ 1024
#define H_ 256
#define M_ (B_*T_)   /* 65536 rows for the projection GEMMs */

// Scratch (device globals — no runtime allocation allowed)
__device__ float g_xp[B_*T_*H_];   // input-projection result for current layer
__device__ float g_h [B_*T_*H_];   // layer-0 hidden sequence

// ---------------------------------------------------------------------------
// packed f32x2 helpers (sm_100+): one instr = 2 fp32 FMAs
// ---------------------------------------------------------------------------
__device__ __forceinline__ unsigned long long ffma2(unsigned long long a,
                                                    unsigned long long b,
                                                    unsigned long long c) {
    unsigned long long d;
    asm("fma.rn.f32x2 %0, %1, %2, %3;" : "=l"(d) : "l"(a), "l"(b), "l"(c));
    return d;
}
__device__ __forceinline__ unsigned long long pack2(float lo, float hi) {
    unsigned long long r;
    asm("mov.b64 %0, {%1, %2};"
        : "=l"(r) : "r"(__float_as_uint(lo)), "r"(__float_as_uint(hi)));
    return r;
}
__device__ __forceinline__ float2 unpack2(unsigned long long v) {
    uint32_t lo, hi;
    asm("mov.b64 {%0, %1}, %2;" : "=r"(lo), "=r"(hi) : "l"(v));
    return make_float2(__uint_as_float(lo), __uint_as_float(hi));
}
__device__ __forceinline__ uint32_t smem_u32(const void* p) {
    return (uint32_t)__cvta_generic_to_shared(p);
}
// Fast accurate-enough tanh: ~1e-7 rel err, MUFU-based (no branches).
__device__ __forceinline__ float tanh_fast(float x) {
    float xc = fminf(fmaxf(x, -9.0f), 9.0f);     // tanh(9)=1-3e-8
    float e  = __expf(2.0f * xc);
    return __fdividef(e - 1.0f, e + 1.0f);
}

// ---------------------------------------------------------------------------
// Projection GEMM: out[M,256] = A[M,256] @ W[256,256]^T + bias
// (unchanged: ~214us each)
// ---------------------------------------------------------------------------
__global__ void __launch_bounds__(256, 2)
gemm_bias(const float* __restrict__ A, const float* __restrict__ W,
          const float* __restrict__ bias, float* __restrict__ out)
{
    __shared__ __align__(16) float As[16][128];
    __shared__ __align__(16) float Bs[16][64];

    const int tid = threadIdx.x;
    const int m0  = blockIdx.x * 128;
    const int n0  = blockIdx.y * 64;
    const int tx  = tid & 15;
    const int ty  = tid >> 4;
    const int lm  = tid >> 1;
    const int ak  = (tid & 1) * 8;
    const int ln  = tid & 63;
    const int bk  = (tid >> 6) * 4;

    unsigned long long acc[4][4];
#pragma unroll
    for (int p = 0; p < 4; p++)
#pragma unroll
        for (int n = 0; n < 4; n++) acc[p][n] = 0ull;

    const float* Arow = A + (size_t)(m0 + lm) * H_;
    const float* Wrow = W + (size_t)(n0 + ln) * H_;

    for (int k0 = 0; k0 < H_; k0 += 16) {
        float4 av0 = *(const float4*)(Arow + k0 + ak);
        float4 av1 = *(const float4*)(Arow + k0 + ak + 4);
        float4 bv0 = *(const float4*)(Wrow + k0 + bk);
        As[ak+0][lm] = av0.x; As[ak+1][lm] = av0.y;
        As[ak+2][lm] = av0.z; As[ak+3][lm] = av0.w;
        As[ak+4][lm] = av1.x; As[ak+5][lm] = av1.y;
        As[ak+6][lm] = av1.z; As[ak+7][lm] = av1.w;
        Bs[bk+0][ln] = bv0.x; Bs[bk+1][ln] = bv0.y;
        Bs[bk+2][ln] = bv0.z; Bs[bk+3][ln] = bv0.w;
        __syncthreads();
#pragma unroll
        for (int k = 0; k < 16; k++) {
            const ulonglong2* ap = (const ulonglong2*)&As[k][ty * 8];
            ulonglong2 q0 = ap[0];
            ulonglong2 q1 = ap[1];
            float4 bv = *(const float4*)&Bs[k][tx * 4];
            unsigned long long b0 = pack2(bv.x, bv.x);
            unsigned long long b1 = pack2(bv.y, bv.y);
            unsigned long long b2 = pack2(bv.z, bv.z);
            unsigned long long b3 = pack2(bv.w, bv.w);
            acc[0][0]=ffma2(q0.x,b0,acc[0][0]); acc[0][1]=ffma2(q0.x,b1,acc[0][1]);
            acc[0][2]=ffma2(q0.x,b2,acc[0][2]); acc[0][3]=ffma2(q0.x,b3,acc[0][3]);
            acc[1][0]=ffma2(q0.y,b0,acc[1][0]); acc[1][1]=ffma2(q0.y,b1,acc[1][1]);
            acc[1][2]=ffma2(q0.y,b2,acc[1][2]); acc[1][3]=ffma2(q0.y,b3,acc[1][3]);
            acc[2][0]=ffma2(q1.x,b0,acc[2][0]); acc[2][1]=ffma2(q1.x,b1,acc[2][1]);
            acc[2][2]=ffma2(q1.x,b2,acc[2][2]); acc[2][3]=ffma2(q1.x,b3,acc[2][3]);
            acc[3][0]=ffma2(q1.y,b0,acc[3][0]); acc[3][1]=ffma2(q1.y,b1,acc[3][1]);
            acc[3][2]=ffma2(q1.y,b2,acc[3][2]); acc[3][3]=ffma2(q1.y,b3,acc[3][3]);
        }
        __syncthreads();
    }

    float4 bb = *(const float4*)(bias + n0 + tx * 4);
#pragma unroll
    for (int p = 0; p < 4; p++) {
        float2 c0 = unpack2(acc[p][0]);
        float2 c1 = unpack2(acc[p][1]);
        float2 c2 = unpack2(acc[p][2]);
        float2 c3 = unpack2(acc[p][3]);
        float4 lo = make_float4(c0.x + bb.x, c1.x + bb.y, c2.x + bb.z, c3.x + bb.w);
        float4 hi = make_float4(c0.y + bb.x, c1.y + bb.y, c2.y + bb.z, c3.y + bb.w);
        size_t r = (size_t)(m0 + ty * 8 + 2 * p) * H_ + n0 + tx * 4;
        *(float4*)(out + r)      = lo;
        *(float4*)(out + r + H_) = hi;
    }
}

// ---------------------------------------------------------------------------
// Recurrent scan, round 7: PARTIAL-SUM exchange (h never crosses the cluster).
//  CTA r owns h-half r. Each step, every thread computes the local-k partial
//  for ONE output j=tid (full 128-k dot, no shfl). Warps owning the PEER's
//  output half st.async their scalar partial to the peer as soon as their
//  FFMA chain retires — the ~215cyc DSMEM flight overlaps the other warps'
//  compute. My-half warps: wait(tx-counted mbar), add peer partial + x, tanh,
//  store h locally. One __syncthreads per step.
//  WAR on pb[t&1] (reused at t+2) is ordered by: peer t+2 send <- peer t+1
//  h-update <- my t+1 send <- my end-of-t bar <- my t read.
//  Phase arming: leader thread (a my-half waiter) re-arms expect_tx(512)
//  immediately after its wait -> arrival always lands in a completed phase.
// ---------------------------------------------------------------------------
__device__ __forceinline__ void mbar_wait_cta(uint32_t mbar, uint32_t parity) {
    asm volatile(
        "{\n\t"
        ".reg .pred P;\n"
        "WAIT_%=:\n\t"
        "mbarrier.try_wait.parity.shared::cta.b64 P, [%0], %1, 0x989680;\n\t"
        "@!P bra WAIT_%=;\n\t"
        "}"
        :: "r"(mbar), "r"(parity) : "memory");
}

__global__ void __launch_bounds__(256, 1) __cluster_dims__(2, 1, 1)
elman_scan(const float* __restrict__ xp, const float* __restrict__ Whh,
           float* __restrict__ ys)
{
    __shared__ __align__(16) float hs[2][128];     // local h half, double-buf
    __shared__ __align__(16) float pb[2][128];     // peer partials, double-buf
    __shared__ __align__(8)  unsigned long long mbar[2];

    const int tid  = threadIdx.x;
    const int rank = (int)(blockIdx.x & 1);
    const int batch= (int)(blockIdx.x >> 1);
    const int j    = tid;              // global output index owned by thread
    const int jl   = tid & 127;        // index within its half
    const bool mine = ((tid >> 7) == rank);   // my-half warps (4 of 8)

    // Weights: W_hh[j][rank*128 .. +127] as 64 packed f32x2 (local k-half)
    unsigned long long w[64];
    {
        const ulonglong2* wv =
            (const ulonglong2*)(Whh + (size_t)j * H_ + rank * 128);
#pragma unroll
        for (int i = 0; i < 32; i++) {
            ulonglong2 v = wv[i];
            w[2*i] = v.x; w[2*i+1] = v.y;
        }
    }

    if (tid < 128) { hs[0][tid] = 0.0f; hs[1][tid] = 0.0f; }
    const uint32_t mb0 = smem_u32(&mbar[0]);
    const int leader = rank << 7;      // a my-half thread
    if (tid == 0) {
        asm volatile("mbarrier.init.shared.b64 [%0], 1;" :: "r"(mb0) : "memory");
        asm volatile("mbarrier.init.shared.b64 [%0], 1;" :: "r"(mb0 + 8) : "memory");
    }
    __syncthreads();
    if (tid == leader) {   // arm phase 0 of both buffers (t=0 and t=1)
        asm volatile("mbarrier.arrive.expect_tx.shared.b64 _, [%0], %1;"
                     :: "r"(mb0), "r"(512u) : "memory");
        asm volatile("mbarrier.arrive.expect_tx.shared.b64 _, [%0], %1;"
                     :: "r"(mb0 + 8), "r"(512u) : "memory");
    }
    __syncthreads();
    // inits/arms visible cluster-wide before any remote traffic
    asm volatile("barrier.cluster.arrive.aligned;" ::: "memory");
    asm volatile("barrier.cluster.wait.aligned;"   ::: "memory");

    const uint32_t pb0 = smem_u32(&pb[0][0]);
    uint32_t peer_pb, peer_mb;
    asm("mapa.shared::cluster.u32 %0, %1, %2;" : "=r"(peer_pb) : "r"(pb0), "r"(rank ^ 1));
    asm("mapa.shared::cluster.u32 %0, %1, %2;" : "=r"(peer_mb) : "r"(mb0), "r"(rank ^ 1));

    const float* xpb = xp + (size_t)batch * T_ * H_;
    float*       ysb = ys + (size_t)batch * T_ * H_;

    float x_cur = 0.0f, x_next = 0.0f;
    if (mine) x_cur = __ldg(xpb + j);      // xp[t=0][j]

    for (int t = 0; t < T_; t++) {
        // Partial over the LOCAL k-half (uniform broadcast reads of hs)
        const ulonglong2* hv = (const ulonglong2*)&hs[t & 1][0];
        unsigned long long a0 = 0ull, a1 = 0ull, a2 = 0ull, a3 = 0ull;
#pragma unroll
        for (int i = 0; i < 16; i++) {
            ulonglong2 p = hv[2*i];
            ulonglong2 q = hv[2*i + 1];
            a0 = ffma2(w[4*i+0], p.x, a0);
            a1 = ffma2(w[4*i+1], p.y, a1);
            a2 = ffma2(w[4*i+2], q.x, a2);
            a3 = ffma2(w[4*i+3], q.y, a3);
        }
        float2 f0 = unpack2(a0), f1 = unpack2(a1);
        float2 f2 = unpack2(a2), f3 = unpack2(a3);
        float s = ((f0.x + f0.y) + (f1.x + f1.y)) +
                  ((f2.x + f2.y) + (f3.x + f3.y));

        if (!mine) {
            // Peer-half warps: ship the partial immediately (flight overlaps
            // the my-half warps' compute). Target buffer t&1 on the peer.
            asm volatile(
                "st.async.shared::cluster.mbarrier::complete_tx::bytes.b32 "
                "[%0], %1, [%2];"
                :: "r"(peer_pb + (uint32_t)((t & 1) * 128 + jl) * 4u),
                   "r"(__float_as_uint(s)),
                   "r"(peer_mb + (uint32_t)(t & 1) * 8u) : "memory");
        } else {
            if (t + 1 < T_)
                x_next = __ldg(xpb + (size_t)(t + 1) * H_ + j);
            mbar_wait_cta(mb0 + (uint32_t)(t & 1) * 8u,
                          (uint32_t)((t >> 1) & 1));
            if (tid == leader && t + 2 < T_) {
                asm volatile("mbarrier.arrive.expect_tx.shared.b64 _, [%0], %1;"
                             :: "r"(mb0 + (uint32_t)(t & 1) * 8u),
                                "r"(512u) : "memory");
            }
            float v = tanh_fast(s + pb[t & 1][jl] + x_cur);
            ysb[(size_t)t * H_ + j] = v;
            hs[(t + 1) & 1][jl] = v;
            x_cur = x_next;
        }
        __syncthreads();   // h visible to all; orders pb read before reuse
    }
}

// ---------------------------------------------------------------------------
// Launch: gemm0 -> scan0 -> gemm1 -> scan1 (all on the capture stream)
// ---------------------------------------------------------------------------
extern "C" void kernel_launch(void* const* d_in, const int* in_sizes, int n_in,
                              void* d_out, int out_size)
{
    const float* x     = (const float*)d_in[0];
    const float* W_ih0 = (const float*)d_in[1];
    const float* b_ih0 = (const float*)d_in[2];
    const float* W_hh0 = (const float*)d_in[3];
    const float* W_ih1 = (const float*)d_in[4];
    const float* b_ih1 = (const float*)d_in[5];
    const float* W_hh1 = (const float*)d_in[6];
    float* out = (float*)d_out;

    float *xp, *h;
    cudaGetSymbolAddress((void**)&xp, g_xp);
    cudaGetSymbolAddress((void**)&h,  g_h);

    dim3 ggrid(M_ / 128, H_ / 64);   // (512, 4)

    gemm_bias<<<ggrid, 256>>>(x, W_ih0, b_ih0, xp);
    elman_scan<<<B_ * 2, 256>>>(xp, W_hh0, h);
    gemm_bias<<<ggrid, 256>>>(h, W_ih1, b_ih1, xp);
    elman_scan<<<B_ * 2, 256>>>(xp, W_hh1, out);
}

// round 8
// speedup vs baseline: 1.3608x; 1.0287x over previous
#include <cuda_runtime.h>
#include <math.h>
#include <stdint.h>

#define B_ 64
#define T_ 1024
#define H_ 256
#define M_ (B_*T_)   /* 65536 rows for the projection GEMMs */

// Scratch (device globals — no runtime allocation allowed)
__device__ float g_xp[B_*T_*H_];   // input-projection result for current layer
__device__ float g_h [B_*T_*H_];   // layer-0 hidden sequence

// ---------------------------------------------------------------------------
// packed f32x2 helpers (sm_100+): one instr = 2 fp32 FMAs
// ---------------------------------------------------------------------------
__device__ __forceinline__ unsigned long long ffma2(unsigned long long a,
                                                    unsigned long long b,
                                                    unsigned long long c) {
    unsigned long long d;
    asm("fma.rn.f32x2 %0, %1, %2, %3;" : "=l"(d) : "l"(a), "l"(b), "l"(c));
    return d;
}
__device__ __forceinline__ unsigned long long pack2(float lo, float hi) {
    unsigned long long r;
    asm("mov.b64 %0, {%1, %2};"
        : "=l"(r) : "r"(__float_as_uint(lo)), "r"(__float_as_uint(hi)));
    return r;
}
__device__ __forceinline__ float2 unpack2(unsigned long long v) {
    uint32_t lo, hi;
    asm("mov.b64 {%0, %1}, %2;" : "=r"(lo), "=r"(hi) : "l"(v));
    return make_float2(__uint_as_float(lo), __uint_as_float(hi));
}
__device__ __forceinline__ uint32_t smem_u32(const void* p) {
    return (uint32_t)__cvta_generic_to_shared(p);
}
// Fast accurate-enough tanh: ~1e-7 rel err, MUFU-based (no branches).
__device__ __forceinline__ float tanh_fast(float x) {
    float xc = fminf(fmaxf(x, -9.0f), 9.0f);     // tanh(9)=1-3e-8
    float e  = __expf(2.0f * xc);
    return __fdividef(e - 1.0f, e + 1.0f);
}

// ---------------------------------------------------------------------------
// Projection GEMM: out[M,256] = A[M,256] @ W[256,256]^T + bias
// (unchanged: ~214us each)
// ---------------------------------------------------------------------------
__global__ void __launch_bounds__(256, 2)
gemm_bias(const float* __restrict__ A, const float* __restrict__ W,
          const float* __restrict__ bias, float* __restrict__ out)
{
    __shared__ __align__(16) float As[16][128];
    __shared__ __align__(16) float Bs[16][64];

    const int tid = threadIdx.x;
    const int m0  = blockIdx.x * 128;
    const int n0  = blockIdx.y * 64;
    const int tx  = tid & 15;
    const int ty  = tid >> 4;
    const int lm  = tid >> 1;
    const int ak  = (tid & 1) * 8;
    const int ln  = tid & 63;
    const int bk  = (tid >> 6) * 4;

    unsigned long long acc[4][4];
#pragma unroll
    for (int p = 0; p < 4; p++)
#pragma unroll
        for (int n = 0; n < 4; n++) acc[p][n] = 0ull;

    const float* Arow = A + (size_t)(m0 + lm) * H_;
    const float* Wrow = W + (size_t)(n0 + ln) * H_;

    for (int k0 = 0; k0 < H_; k0 += 16) {
        float4 av0 = *(const float4*)(Arow + k0 + ak);
        float4 av1 = *(const float4*)(Arow + k0 + ak + 4);
        float4 bv0 = *(const float4*)(Wrow + k0 + bk);
        As[ak+0][lm] = av0.x; As[ak+1][lm] = av0.y;
        As[ak+2][lm] = av0.z; As[ak+3][lm] = av0.w;
        As[ak+4][lm] = av1.x; As[ak+5][lm] = av1.y;
        As[ak+6][lm] = av1.z; As[ak+7][lm] = av1.w;
        Bs[bk+0][ln] = bv0.x; Bs[bk+1][ln] = bv0.y;
        Bs[bk+2][ln] = bv0.z; Bs[bk+3][ln] = bv0.w;
        __syncthreads();
#pragma unroll
        for (int k = 0; k < 16; k++) {
            const ulonglong2* ap = (const ulonglong2*)&As[k][ty * 8];
            ulonglong2 q0 = ap[0];
            ulonglong2 q1 = ap[1];
            float4 bv = *(const float4*)&Bs[k][tx * 4];
            unsigned long long b0 = pack2(bv.x, bv.x);
            unsigned long long b1 = pack2(bv.y, bv.y);
            unsigned long long b2 = pack2(bv.z, bv.z);
            unsigned long long b3 = pack2(bv.w, bv.w);
            acc[0][0]=ffma2(q0.x,b0,acc[0][0]); acc[0][1]=ffma2(q0.x,b1,acc[0][1]);
            acc[0][2]=ffma2(q0.x,b2,acc[0][2]); acc[0][3]=ffma2(q0.x,b3,acc[0][3]);
            acc[1][0]=ffma2(q0.y,b0,acc[1][0]); acc[1][1]=ffma2(q0.y,b1,acc[1][1]);
            acc[1][2]=ffma2(q0.y,b2,acc[1][2]); acc[1][3]=ffma2(q0.y,b3,acc[1][3]);
            acc[2][0]=ffma2(q1.x,b0,acc[2][0]); acc[2][1]=ffma2(q1.x,b1,acc[2][1]);
            acc[2][2]=ffma2(q1.x,b2,acc[2][2]); acc[2][3]=ffma2(q1.x,b3,acc[2][3]);
            acc[3][0]=ffma2(q1.y,b0,acc[3][0]); acc[3][1]=ffma2(q1.y,b1,acc[3][1]);
            acc[3][2]=ffma2(q1.y,b2,acc[3][2]); acc[3][3]=ffma2(q1.y,b3,acc[3][3]);
        }
        __syncthreads();
    }

    float4 bb = *(const float4*)(bias + n0 + tx * 4);
#pragma unroll
    for (int p = 0; p < 4; p++) {
        float2 c0 = unpack2(acc[p][0]);
        float2 c1 = unpack2(acc[p][1]);
        float2 c2 = unpack2(acc[p][2]);
        float2 c3 = unpack2(acc[p][3]);
        float4 lo = make_float4(c0.x + bb.x, c1.x + bb.y, c2.x + bb.z, c3.x + bb.w);
        float4 hi = make_float4(c0.y + bb.x, c1.y + bb.y, c2.y + bb.z, c3.y + bb.w);
        size_t r = (size_t)(m0 + ty * 8 + 2 * p) * H_ + n0 + tx * 4;
        *(float4*)(out + r)      = lo;
        *(float4*)(out + r + H_) = hi;
    }
}

// ---------------------------------------------------------------------------
// Recurrent scan, round 8: partial-sum exchange with VECTORIZED st.async.
//  Identical dataflow to round 7 (CTA r owns h-half r; partials cross the
//  cluster), but senders gather 4 partials per lane-quad via 3 shfl.down and
//  ship ONE st.async.v4.b32 (16B) per quad: 32 messages/phase instead of 128.
//  Theory under test: per-message mbarrier complete_tx accounting (not bytes)
//  is the ~1000cyc serial segment.
//  expect_tx stays 512 B (32 x 16B). Everything else unchanged.
// ---------------------------------------------------------------------------
__device__ __forceinline__ void mbar_wait_cta(uint32_t mbar, uint32_t parity) {
    asm volatile(
        "{\n\t"
        ".reg .pred P;\n"
        "WAIT_%=:\n\t"
        "mbarrier.try_wait.parity.shared::cta.b64 P, [%0], %1, 0x989680;\n\t"
        "@!P bra WAIT_%=;\n\t"
        "}"
        :: "r"(mbar), "r"(parity) : "memory");
}

__global__ void __launch_bounds__(256, 1) __cluster_dims__(2, 1, 1)
elman_scan(const float* __restrict__ xp, const float* __restrict__ Whh,
           float* __restrict__ ys)
{
    __shared__ __align__(16) float hs[2][128];     // local h half, double-buf
    __shared__ __align__(16) float pb[2][128];     // peer partials, double-buf
    __shared__ __align__(8)  unsigned long long mbar[2];

    const int tid  = threadIdx.x;
    const int rank = (int)(blockIdx.x & 1);
    const int batch= (int)(blockIdx.x >> 1);
    const int j    = tid;              // global output index owned by thread
    const int jl   = tid & 127;        // index within its half
    const bool mine = ((tid >> 7) == rank);   // my-half warps (4 of 8)

    // Weights: W_hh[j][rank*128 .. +127] as 64 packed f32x2 (local k-half)
    unsigned long long w[64];
    {
        const ulonglong2* wv =
            (const ulonglong2*)(Whh + (size_t)j * H_ + rank * 128);
#pragma unroll
        for (int i = 0; i < 32; i++) {
            ulonglong2 v = wv[i];
            w[2*i] = v.x; w[2*i+1] = v.y;
        }
    }

    if (tid < 128) { hs[0][tid] = 0.0f; hs[1][tid] = 0.0f; }
    const uint32_t mb0 = smem_u32(&mbar[0]);
    const int leader = rank << 7;      // a my-half thread
    if (tid == 0) {
        asm volatile("mbarrier.init.shared.b64 [%0], 1;" :: "r"(mb0) : "memory");
        asm volatile("mbarrier.init.shared.b64 [%0], 1;" :: "r"(mb0 + 8) : "memory");
    }
    __syncthreads();
    if (tid == leader) {   // arm phase 0 of both buffers (t=0 and t=1)
        asm volatile("mbarrier.arrive.expect_tx.shared.b64 _, [%0], %1;"
                     :: "r"(mb0), "r"(512u) : "memory");
        asm volatile("mbarrier.arrive.expect_tx.shared.b64 _, [%0], %1;"
                     :: "r"(mb0 + 8), "r"(512u) : "memory");
    }
    __syncthreads();
    // inits/arms visible cluster-wide before any remote traffic
    asm volatile("barrier.cluster.arrive.aligned;" ::: "memory");
    asm volatile("barrier.cluster.wait.aligned;"   ::: "memory");

    const uint32_t pb0 = smem_u32(&pb[0][0]);
    uint32_t peer_pb, peer_mb;
    asm("mapa.shared::cluster.u32 %0, %1, %2;" : "=r"(peer_pb) : "r"(pb0), "r"(rank ^ 1));
    asm("mapa.shared::cluster.u32 %0, %1, %2;" : "=r"(peer_mb) : "r"(mb0), "r"(rank ^ 1));

    const float* xpb = xp + (size_t)batch * T_ * H_;
    float*       ysb = ys + (size_t)batch * T_ * H_;

    float x_cur = 0.0f, x_next = 0.0f;
    if (mine) x_cur = __ldg(xpb + j);      // xp[t=0][j]

    for (int t = 0; t < T_; t++) {
        // Partial over the LOCAL k-half (uniform broadcast reads of hs)
        const ulonglong2* hv = (const ulonglong2*)&hs[t & 1][0];
        unsigned long long a0 = 0ull, a1 = 0ull, a2 = 0ull, a3 = 0ull;
#pragma unroll
        for (int i = 0; i < 16; i++) {
            ulonglong2 p = hv[2*i];
            ulonglong2 q = hv[2*i + 1];
            a0 = ffma2(w[4*i+0], p.x, a0);
            a1 = ffma2(w[4*i+1], p.y, a1);
            a2 = ffma2(w[4*i+2], q.x, a2);
            a3 = ffma2(w[4*i+3], q.y, a3);
        }
        float2 f0 = unpack2(a0), f1 = unpack2(a1);
        float2 f2 = unpack2(a2), f3 = unpack2(a3);
        float s = ((f0.x + f0.y) + (f1.x + f1.y)) +
                  ((f2.x + f2.y) + (f3.x + f3.y));

        if (!mine) {
            // Gather 4 partials into the quad-base lane (3 indep shfls),
            // then ONE 16B async message per quad: 32 messages per phase.
            float v1 = __shfl_down_sync(0xFFFFFFFFu, s, 1);
            float v2 = __shfl_down_sync(0xFFFFFFFFu, s, 2);
            float v3 = __shfl_down_sync(0xFFFFFFFFu, s, 3);
            if ((jl & 3) == 0) {
                asm volatile(
                    "st.async.shared::cluster.mbarrier::complete_tx::bytes"
                    ".v4.b32 [%0], {%1, %2, %3, %4}, [%5];"
                    :: "r"(peer_pb + (uint32_t)((t & 1) * 128 + jl) * 4u),
                       "r"(__float_as_uint(s)),  "r"(__float_as_uint(v1)),
                       "r"(__float_as_uint(v2)), "r"(__float_as_uint(v3)),
                       "r"(peer_mb + (uint32_t)(t & 1) * 8u) : "memory");
            }
        } else {
            if (t + 1 < T_)
                x_next = __ldg(xpb + (size_t)(t + 1) * H_ + j);
            mbar_wait_cta(mb0 + (uint32_t)(t & 1) * 8u,
                          (uint32_t)((t >> 1) & 1));
            if (tid == leader && t + 2 < T_) {
                asm volatile("mbarrier.arrive.expect_tx.shared.b64 _, [%0], %1;"
                             :: "r"(mb0 + (uint32_t)(t & 1) * 8u),
                                "r"(512u) : "memory");
            }
            float v = tanh_fast(s + pb[t & 1][jl] + x_cur);
            hs[(t + 1) & 1][jl] = v;
            ysb[(size_t)t * H_ + j] = v;
            x_cur = x_next;
        }
        __syncthreads();   // h visible to all; orders pb read before reuse
    }
}

// ---------------------------------------------------------------------------
// Launch: gemm0 -> scan0 -> gemm1 -> scan1 (all on the capture stream)
// ---------------------------------------------------------------------------
extern "C" void kernel_launch(void* const* d_in, const int* in_sizes, int n_in,
                              void* d_out, int out_size)
{
    const float* x     = (const float*)d_in[0];
    const float* W_ih0 = (const float*)d_in[1];
    const float* b_ih0 = (const float*)d_in[2];
    const float* W_hh0 = (const float*)d_in[3];
    const float* W_ih1 = (const float*)d_in[4];
    const float* b_ih1 = (const float*)d_in[5];
    const float* W_hh1 = (const float*)d_in[6];
    float* out = (float*)d_out;

    float *xp, *h;
    cudaGetSymbolAddress((void**)&xp, g_xp);
    cudaGetSymbolAddress((void**)&h,  g_h);

    dim3 ggrid(M_ / 128, H_ / 64);   // (512, 4)

    gemm_bias<<<ggrid, 256>>>(x, W_ih0, b_ih0, xp);
    elman_scan<<<B_ * 2, 256>>>(xp, W_hh0, h);
    gemm_bias<<<ggrid, 256>>>(h, W_ih1, b_ih1, xp);
    elman_scan<<<B_ * 2, 256>>>(xp, W_hh1, out);
}